// round 5
// baseline (speedup 1.0000x reference)
#include <cuda_runtime.h>
#include <cstdint>

#define Bn 16
#define Cc 128
#define Hh 64
#define Ww 64

// ---- scratch: tf32-pre-rounded weights [b][tap][co][ci] and inputs [b][ci][h][w] ----
__device__ uint32_t g_wt[(size_t)Bn * 9 * Cc * Cc];
__device__ uint32_t g_xt[(size_t)Bn * Cc * Hh * Ww];

__device__ __forceinline__ uint32_t f2tf32(float x) {
    uint32_t r;
    asm("cvt.rna.tf32.f32 %0, %1;" : "=r"(r) : "f"(x));
    return r;
}

// fused prep: blocks [0, 4608) transpose+round W; blocks [4608, 8704) round X
#define W_BLOCKS 4608
__global__ void prep_all(const float* __restrict__ w, const float* __restrict__ x) {
    if (blockIdx.x < W_BLOCKS) {
        int idx = blockIdx.x * 512 + threadIdx.x;   // 2359296 total
        int ci   = idx & 127;
        int co   = (idx >> 7) & 127;
        int rest = idx >> 14;                       // b*9 + t
        int t    = rest % 9;
        int b    = rest / 9;
        g_wt[idx] = f2tf32(w[((size_t)(b * Cc + co) * Cc + ci) * 9 + t]);
    } else {
        int idx = (blockIdx.x - W_BLOCKS) * 512 + threadIdx.x;  // 2097152 float4s
        float4 v = ((const float4*)x)[idx];
        uint4 u;
        u.x = f2tf32(v.x); u.y = f2tf32(v.y);
        u.z = f2tf32(v.z); u.w = f2tf32(v.w);
        ((uint4*)g_xt)[idx] = u;
    }
}

// ---- main kernel (round-3 geometry, all-async staging) ----
// CTA: M=128 (all co) x N=256 (4 rows x 64 w), K in 16 chunks of 8 ci. 512 thr, 1 CTA/SM.
// X tile [8 ci][6 rows][76], ci-stride 456 (==8 mod 32), row-stride 76; w=0 at slot 4.
// W tile [9 tap][128 co][12], co-stride 12 (conflict-free A frags).
#define XBUF_F 3648
#define WBUF_F 13824
#define X_CI   456
#define X_ROW  76
#define W_TAP  1536
#define W_CO   12

__device__ __forceinline__ uint32_t s2u(const void* p) {
    uint32_t a;
    asm("{ .reg .u64 t; cvta.to.shared.u64 t, %1; cvt.u32.u64 %0, t; }" : "=r"(a) : "l"(p));
    return a;
}

#define CP16(dst_u32, src_ptr) \
    asm volatile("cp.async.cg.shared.global [%0], [%1], 16;" :: "r"(dst_u32), "l"(src_ptr))

#define MMA_TF32(c, a, b0v, b1v)                                                  \
    asm volatile("mma.sync.aligned.m16n8k8.row.col.f32.tf32.tf32.f32 "            \
                 "{%0,%1,%2,%3}, {%4,%5,%6,%7}, {%8,%9}, {%0,%1,%2,%3};"          \
                 : "+f"((c)[0]), "+f"((c)[1]), "+f"((c)[2]), "+f"((c)[3])         \
                 : "r"((a)[0]), "r"((a)[1]), "r"((a)[2]), "r"((a)[3]),            \
                   "r"(b0v), "r"(b1v))

__global__ __launch_bounds__(512, 1)
void resconv_mma(const float* __restrict__ inp, float* __restrict__ out)
{
    extern __shared__ float smf[];
    uint32_t* smu = (uint32_t*)smf;

    const int tid  = threadIdx.x;
    const int lane = tid & 31;
    const int wid  = tid >> 5;
    const int wm   = wid & 1;        // 0..1 : co half (64)
    const int wn   = wid >> 1;       // 0..7 : n group (32)
    const int lr   = lane >> 2;      // 0..7
    const int lc   = lane & 3;       // 0..3

    const int h0 = blockIdx.x * 4;
    const int b  = blockIdx.y;

    const uint32_t sbase = s2u(smf);
    const uint32_t* xsrc = g_xt + (size_t)b * Cc * Hh * Ww;
    const uint32_t* wsrc = g_wt + (size_t)b * 9 * Cc * Cc;

    // zero X buffers once (halo zeros are loop-invariant)
    for (int i = tid; i < 2 * XBUF_F; i += 512) smf[i] = 0.f;
    __syncthreads();

    float acc[4][4][4];
#pragma unroll
    for (int i = 0; i < 4; i++)
#pragma unroll
        for (int j = 0; j < 4; j++)
#pragma unroll
            for (int k = 0; k < 4; k++) acc[i][j][k] = 0.f;

    auto stageX = [&](int ci0, int xoff) {
#pragma unroll
        for (int it = 0; it < 2; it++) {
            int idx = tid + it * 512;
            if (idx < 768) {
                int ci  = idx / 96;
                int rem = idx - ci * 96;
                int row = rem >> 4;
                int seg = rem & 15;
                int gh  = h0 + row - 1;
                if ((unsigned)gh < (unsigned)Hh) {
                    const uint32_t* src = xsrc + ((size_t)(ci0 + ci) * Hh + gh) * Ww + seg * 4;
                    uint32_t dst = sbase + 4u * (uint32_t)(xoff + ci * X_CI + row * X_ROW + 4 + seg * 4);
                    CP16(dst, src);
                }
            }
        }
    };
    auto stageW = [&](int ci0, int woff) {
#pragma unroll
        for (int it = 0; it < 5; it++) {
            int idx = tid + it * 512;
            if (idx < 2304) {
                int half = idx & 1;
                int co   = (idx >> 1) & 127;
                int tap  = idx >> 8;
                const uint32_t* src = wsrc + ((size_t)tap * Cc + co) * Cc + ci0 + half * 4;
                uint32_t dst = sbase + 4u * (uint32_t)(woff + tap * W_TAP + co * W_CO + half * 4);
                CP16(dst, src);
            }
        }
        asm volatile("cp.async.commit_group;" ::: "memory");
    };

    stageX(0, 0);
    stageW(0, 2 * XBUF_F);
    asm volatile("cp.async.wait_group 0;" ::: "memory");
    __syncthreads();

    for (int kc = 0; kc < 16; kc++) {
        const int cur  = kc & 1;
        const int xoff = cur * XBUF_F;
        const int woff = 2 * XBUF_F + cur * WBUF_F;

        if (kc < 15) {
            stageX((kc + 1) * 8, (cur ^ 1) * XBUF_F);
            stageW((kc + 1) * 8, 2 * XBUF_F + (cur ^ 1) * WBUF_F);
        }

#pragma unroll
        for (int kh = 0; kh < 3; kh++) {
#pragma unroll
            for (int kw = 0; kw < 3; kw++) {
                const int t = kh * 3 + kw;
                uint32_t a[4][4];
#pragma unroll
                for (int tm = 0; tm < 4; tm++) {
                    const int cob = wm * 64 + tm * 16 + lr;
                    const uint32_t* p = smu + woff + t * W_TAP + cob * W_CO + lc;
                    a[tm][0] = p[0];
                    a[tm][1] = p[8 * W_CO];
                    a[tm][2] = p[4];
                    a[tm][3] = p[8 * W_CO + 4];
                }
#pragma unroll
                for (int tn = 0; tn < 4; tn++) {
                    const int n0 = wn * 32 + tn * 8;
                    const int r  = n0 >> 6;
                    const int x  = (n0 & 63) + lr;
                    const uint32_t* q = smu + xoff + lc * X_CI + (r + kh) * X_ROW + x + kw + 3;
                    uint32_t b0 = q[0];
                    uint32_t b1 = q[4 * X_CI];
#pragma unroll
                    for (int tm = 0; tm < 4; tm++)
                        MMA_TF32(acc[tm][tn], a[tm], b0, b1);
                }
            }
        }

        asm volatile("cp.async.wait_group 0;" ::: "memory");
        __syncthreads();
    }

    // epilogue: out = inp + conv
#pragma unroll
    for (int tm = 0; tm < 4; tm++) {
#pragma unroll
        for (int tn = 0; tn < 4; tn++) {
            const int n = wn * 32 + tn * 8 + lc * 2;
            const int h = h0 + (n >> 6);
            const int w = n & 63;
            const int co0 = wm * 64 + tm * 16 + lr;
#pragma unroll
            for (int half = 0; half < 2; half++) {
                const int co = co0 + half * 8;
                const size_t off = ((size_t)(b * Cc + co) * Hh + h) * Ww + w;
                float2 rv = *(const float2*)(inp + off);
                float2 ov;
                ov.x = rv.x + acc[tm][tn][half * 2 + 0];
                ov.y = rv.y + acc[tm][tn][half * 2 + 1];
                *(float2*)(out + off) = ov;
            }
        }
    }
}

extern "C" void kernel_launch(void* const* d_in, const int* in_sizes, int n_in,
                              void* d_out, int out_size)
{
    const float* inp = (const float*)d_in[0];   // [16,128,64,64]
    const float* wgt = (const float*)d_in[1];   // [16,128,128,3,3]
    float* out = (float*)d_out;

    prep_all<<<W_BLOCKS + 4096, 512>>>(wgt, inp);

    const int smem_bytes = (2 * XBUF_F + 2 * WBUF_F) * 4;   // 139776
    cudaFuncSetAttribute(resconv_mma, cudaFuncAttributeMaxDynamicSharedMemorySize, smem_bytes);
    dim3 grid(Hh / 4, Bn);   // (16, 16) = 256 CTAs
    resconv_mma<<<grid, 512, smem_bytes>>>(inp, out);
}

// round 6
// speedup vs baseline: 1.0201x; 1.0201x over previous
#include <cuda_runtime.h>
#include <cstdint>

#define Bn 16
#define Cc 128
#define Hh 64
#define Ww 64

// ---- scratch: tf32 weights [b][tap][co][ci]; tf32 inputs interleaved [b][chunk16][pair4][h][w][2]
// where pair p within chunk c holds ci = c*8+p (slot 0) and c*8+p+4 (slot 1) — matches the
// m16n8k8 B-fragment k mapping (b0: k=lc, b1: k=lc+4) so one 8B LDS yields both frags.
__device__ uint32_t g_wt[(size_t)Bn * 9 * Cc * Cc];
__device__ uint32_t g_xt[(size_t)Bn * Cc * Hh * Ww];

__device__ __forceinline__ uint32_t f2tf32(float x) {
    uint32_t r;
    asm("cvt.rna.tf32.f32 %0, %1;" : "=r"(r) : "f"(x));
    return r;
}

#define W_BLOCKS 4608
__global__ void prep_all(const float* __restrict__ w, const float* __restrict__ x) {
    if (blockIdx.x < W_BLOCKS) {
        int idx = blockIdx.x * 512 + threadIdx.x;   // 2359296 total
        int ci   = idx & 127;
        int co   = (idx >> 7) & 127;
        int rest = idx >> 14;                       // b*9 + t
        int t    = rest % 9;
        int b    = rest / 9;
        g_wt[idx] = f2tf32(w[((size_t)(b * Cc + co) * Cc + ci) * 9 + t]);
    } else {
        int u = (blockIdx.x - W_BLOCKS) * 512 + threadIdx.x;  // 2097152 uint4s
        int w4 = u & 31;            // 2 gw per uint4
        int h  = (u >> 5) & 63;
        int pr = (u >> 11) & 3;
        int ch = (u >> 13) & 15;
        int b  = u >> 17;
        int ci = ch * 8 + pr;
        const float* base = x + ((size_t)(b * Cc + ci) * Hh + h) * Ww + w4 * 2;
        float2 v0 = *(const float2*)base;
        float2 v1 = *(const float2*)(base + 4 * Hh * Ww);
        uint4 o;
        o.x = f2tf32(v0.x); o.y = f2tf32(v1.x);
        o.z = f2tf32(v0.y); o.w = f2tf32(v1.y);
        ((uint4*)g_xt)[u] = o;
    }
}

// ---- main kernel ----
// CTA: M=128 (all co) x N=256 (4 rows x 64 w), K in 16 chunks of 8 ci. 512 thr, 1 CTA/SM.
// X tile [4 pair][6 rows][76 w-slots][2], pair stride 912 fl (==16 mod 32: 2-cyc-optimal v2 LDS),
//   row stride 152 fl, w=0 at slot 4 (word 8).
// W tile [9 tap][128 co][12], co-stride 12 (conflict-free A frags).
#define XBUF_F 3648
#define WBUF_F 13824
#define XP     912
#define XR     152
#define W_TAP  1536
#define W_CO   12

__device__ __forceinline__ uint32_t s2u(const void* p) {
    uint32_t a;
    asm("{ .reg .u64 t; cvta.to.shared.u64 t, %1; cvt.u32.u64 %0, t; }" : "=r"(a) : "l"(p));
    return a;
}

#define CP16(dst_u32, src_ptr) \
    asm volatile("cp.async.cg.shared.global [%0], [%1], 16;" :: "r"(dst_u32), "l"(src_ptr))

#define MMA_TF32(c, a, b0v, b1v)                                                  \
    asm volatile("mma.sync.aligned.m16n8k8.row.col.f32.tf32.tf32.f32 "            \
                 "{%0,%1,%2,%3}, {%4,%5,%6,%7}, {%8,%9}, {%0,%1,%2,%3};"          \
                 : "+f"((c)[0]), "+f"((c)[1]), "+f"((c)[2]), "+f"((c)[3])         \
                 : "r"((a)[0]), "r"((a)[1]), "r"((a)[2]), "r"((a)[3]),            \
                   "r"(b0v), "r"(b1v))

__global__ __launch_bounds__(512, 1)
void resconv_mma(const float* __restrict__ inp, float* __restrict__ out)
{
    extern __shared__ float smf[];
    uint32_t* smu = (uint32_t*)smf;

    const int tid  = threadIdx.x;
    const int lane = tid & 31;
    const int wid  = tid >> 5;
    const int wm   = wid & 1;        // 0..1 : co half (64)
    const int wn   = wid >> 1;       // 0..7 : n group (32)
    const int lr   = lane >> 2;      // 0..7
    const int lc   = lane & 3;       // 0..3
    const int trot = wid % 9;        // per-warp tap rotation (de-convoy)

    const int rk = wn >> 1;                  // output row base within tile (constant per warp)
    const int xb = (wn & 1) * 32 + lr;       // w base; + tn*8 per tile

    const int h0 = blockIdx.x * 4;
    const int b  = blockIdx.y;

    const uint32_t sbase = s2u(smf);
    const uint32_t* wsrc = g_wt + (size_t)b * 9 * Cc * Cc;

    // zero X buffers once (halo zeros are loop-invariant)
    for (int i = tid; i < 2 * XBUF_F; i += 512) smf[i] = 0.f;
    __syncthreads();

    float acc[4][4][4];
#pragma unroll
    for (int i = 0; i < 4; i++)
#pragma unroll
        for (int j = 0; j < 4; j++)
#pragma unroll
            for (int k = 0; k < 4; k++) acc[i][j][k] = 0.f;

    auto stageX = [&](int chunk, int xoff) {
#pragma unroll
        for (int it = 0; it < 2; it++) {
            int idx = tid + it * 512;
            if (idx < 768) {                     // [pair 4][row 6][seg 32]
                int pr  = idx / 192;
                int rem = idx - pr * 192;
                int row = rem >> 5;
                int seg = rem & 31;
                int gh  = h0 + row - 1;
                if ((unsigned)gh < (unsigned)Hh) {
                    const uint4* src = (const uint4*)g_xt +
                        ((((size_t)b * 16 + chunk) * 4 + pr) * 64 + gh) * 32 + seg;
                    uint32_t dst = sbase + 4u * (uint32_t)(xoff + pr * XP + row * XR + 8 + seg * 4);
                    CP16(dst, src);
                }
            }
        }
    };
    auto stageW = [&](int ci0, int woff) {
#pragma unroll
        for (int it = 0; it < 5; it++) {
            int idx = tid + it * 512;
            if (idx < 2304) {
                int half = idx & 1;
                int co   = (idx >> 1) & 127;
                int tap  = idx >> 8;
                const uint32_t* src = wsrc + ((size_t)tap * Cc + co) * Cc + ci0 + half * 4;
                uint32_t dst = sbase + 4u * (uint32_t)(woff + tap * W_TAP + co * W_CO + half * 4);
                CP16(dst, src);
            }
        }
        asm volatile("cp.async.commit_group;" ::: "memory");
    };

    stageX(0, 0);
    stageW(0, 2 * XBUF_F);
    asm volatile("cp.async.wait_group 0;" ::: "memory");
    __syncthreads();

    for (int kc = 0; kc < 16; kc++) {
        const int cur  = kc & 1;
        const int xoff = cur * XBUF_F;
        const int woff = 2 * XBUF_F + cur * WBUF_F;

        if (kc < 15) {
            stageX(kc + 1, (cur ^ 1) * XBUF_F);
            stageW((kc + 1) * 8, 2 * XBUF_F + (cur ^ 1) * WBUF_F);
        }

        const uint32_t* xwarp = smu + xoff + lc * XP + rk * XR + (xb + 3) * 2;

#pragma unroll
        for (int tp = 0; tp < 9; tp++) {
            int t = tp + trot;
            if (t >= 9) t -= 9;
            int kh = t / 3;
            int kw = t - kh * 3;

            const uint32_t* pw = smu + woff + t * W_TAP;
            uint32_t a[4][4];
#pragma unroll
            for (int tm = 0; tm < 4; tm++) {
                const int cob = wm * 64 + tm * 16 + lr;
                const uint32_t* p = pw + cob * W_CO + lc;
                a[tm][0] = p[0];
                a[tm][1] = p[8 * W_CO];
                a[tm][2] = p[4];
                a[tm][3] = p[8 * W_CO + 4];
            }
            const uint32_t* xq = xwarp + kh * XR + kw * 2;
#pragma unroll
            for (int tn = 0; tn < 4; tn++) {
                uint2 bb = *(const uint2*)(xq + tn * 16);
#pragma unroll
                for (int tm = 0; tm < 4; tm++)
                    MMA_TF32(acc[tm][tn], a[tm], bb.x, bb.y);
            }
        }

        asm volatile("cp.async.wait_group 0;" ::: "memory");
        __syncthreads();
    }

    // epilogue: out = inp + conv
#pragma unroll
    for (int tm = 0; tm < 4; tm++) {
#pragma unroll
        for (int tn = 0; tn < 4; tn++) {
            const int n = wn * 32 + tn * 8 + lc * 2;
            const int h = h0 + (n >> 6);
            const int w = n & 63;
            const int co0 = wm * 64 + tm * 16 + lr;
#pragma unroll
            for (int half = 0; half < 2; half++) {
                const int co = co0 + half * 8;
                const size_t off = ((size_t)(b * Cc + co) * Hh + h) * Ww + w;
                float2 rv = *(const float2*)(inp + off);
                float2 ov;
                ov.x = rv.x + acc[tm][tn][half * 2 + 0];
                ov.y = rv.y + acc[tm][tn][half * 2 + 1];
                *(float2*)(out + off) = ov;
            }
        }
    }
}

extern "C" void kernel_launch(void* const* d_in, const int* in_sizes, int n_in,
                              void* d_out, int out_size)
{
    const float* inp = (const float*)d_in[0];   // [16,128,64,64]
    const float* wgt = (const float*)d_in[1];   // [16,128,128,3,3]
    float* out = (float*)d_out;

    prep_all<<<W_BLOCKS + 4096, 512>>>(wgt, inp);

    const int smem_bytes = (2 * XBUF_F + 2 * WBUF_F) * 4;   // 139776
    cudaFuncSetAttribute(resconv_mma, cudaFuncAttributeMaxDynamicSharedMemorySize, smem_bytes);
    dim3 grid(Hh / 4, Bn);   // (16, 16) = 256 CTAs
    resconv_mma<<<grid, 512, smem_bytes>>>(inp, out);
}

// round 7
// speedup vs baseline: 1.2455x; 1.2209x over previous
#include <cuda_runtime.h>
#include <cstdint>

#define Bn 16
#define Cc 128
#define Hh 64
#define Ww 64

// ---- scratch ----
// g_wt4: W in fragment-vector layout, uint4[b][chunk16][tap9][cb8][r8][c4]
//   uint4 = tf32 bits of { W(co=cb*16+r, k=c), W(co+8, k=c), W(co, k=c+4), W(co+8, k=c+4) }
//   (k = ci within the 8-ci chunk) — exactly one m16n8k8 A-fragment per lane via LDS.128.
// g_xt: X tf32, pair-interleaved [b][chunk16][pair4][h][w-pair32] uint4 (as round 6).
__device__ uint4 g_wt4[(size_t)Bn * 16 * 9 * 8 * 8 * 4];
__device__ uint32_t g_xt[(size_t)Bn * Cc * Hh * Ww];

__device__ __forceinline__ uint32_t f2tf32(float x) {
    uint32_t r;
    asm("cvt.rna.tf32.f32 %0, %1;" : "=r"(r) : "f"(x));
    return r;
}

// ---- prep W: coalesced read of [b][16 co][128 ci][9 t], smem transpose, frag-vector write ----
__global__ void prep_w_t(const float* __restrict__ w) {
    extern __shared__ float s[];            // [16 co][1152]
    const int b  = blockIdx.x >> 3;
    const int cb = blockIdx.x & 7;
    const float* src = w + ((size_t)b * Cc + cb * 16) * 1152;
#pragma unroll
    for (int it = 0; it < 9; it++) {
        int idx = threadIdx.x + it * 512;   // 4608 uint4
        ((uint4*)s)[idx] = ((const uint4*)src)[idx];
    }
    __syncthreads();
#pragma unroll
    for (int it = 0; it < 9; it++) {
        int idx  = threadIdx.x + it * 512;  // 4608 outputs: ((ch*9+t)*8+r)*4+c
        int c    = idx & 3;
        int r    = (idx >> 2) & 7;
        int rest = idx >> 5;
        int t    = rest % 9;
        int ch   = rest / 9;
        uint4 o;
        o.x = f2tf32(s[ r      * 1152 + (ch * 8 + c    ) * 9 + t]);
        o.y = f2tf32(s[(r + 8) * 1152 + (ch * 8 + c    ) * 9 + t]);
        o.z = f2tf32(s[ r      * 1152 + (ch * 8 + c + 4) * 9 + t]);
        o.w = f2tf32(s[(r + 8) * 1152 + (ch * 8 + c + 4) * 9 + t]);
        g_wt4[((((size_t)(b * 16 + ch) * 9 + t) * 8 + cb) * 8 + r) * 4 + c] = o;
    }
}

// ---- prep X: tf32 round + (ci, ci+4) pair interleave (round-6 layout) ----
__global__ void prep_x(const float* __restrict__ x) {
    int u  = blockIdx.x * 512 + threadIdx.x;   // 2097152 uint4s
    int w4 = u & 31;
    int h  = (u >> 5) & 63;
    int pr = (u >> 11) & 3;
    int ch = (u >> 13) & 15;
    int b  = u >> 17;
    int ci = ch * 8 + pr;
    const float* base = x + ((size_t)(b * Cc + ci) * Hh + h) * Ww + w4 * 2;
    float2 v0 = *(const float2*)base;
    float2 v1 = *(const float2*)(base + 4 * Hh * Ww);
    uint4 o;
    o.x = f2tf32(v0.x); o.y = f2tf32(v1.x);
    o.z = f2tf32(v0.y); o.w = f2tf32(v1.y);
    ((uint4*)g_xt)[u] = o;
}

// ---- main kernel ----
// CTA: M=128 co x N=256 (4 rows x 64 w), 8 warps, warp tile 64x64. 16 K-chunks of 8 ci.
// X tile [4 pair][6 rows][76 slots][2], pair stride 912 fl, row stride 152; w=0 at slot 4.
// W tile: 2304 uint4 per buffer, contiguous copy of g_wt4 chunk; frag at (t*8+cb)*32+lr*4+lc.
#define XBUF_F 3648
#define WBUF_U4 2304
#define XP 912
#define XR 152

__device__ __forceinline__ uint32_t s2u(const void* p) {
    uint32_t a;
    asm("{ .reg .u64 t; cvta.to.shared.u64 t, %1; cvt.u32.u64 %0, t; }" : "=r"(a) : "l"(p));
    return a;
}

#define CP16(dst_u32, src_ptr) \
    asm volatile("cp.async.cg.shared.global [%0], [%1], 16;" :: "r"(dst_u32), "l"(src_ptr))

#define MMA_TF32(c, a0, a1, a2, a3, b0v, b1v)                                     \
    asm volatile("mma.sync.aligned.m16n8k8.row.col.f32.tf32.tf32.f32 "            \
                 "{%0,%1,%2,%3}, {%4,%5,%6,%7}, {%8,%9}, {%0,%1,%2,%3};"          \
                 : "+f"((c)[0]), "+f"((c)[1]), "+f"((c)[2]), "+f"((c)[3])         \
                 : "r"(a0), "r"(a1), "r"(a2), "r"(a3), "r"(b0v), "r"(b1v))

__global__ __launch_bounds__(256, 1)
void resconv_mma(const float* __restrict__ inp, float* __restrict__ out)
{
    extern __shared__ float smf[];
    uint32_t* smu = (uint32_t*)smf;

    const int tid  = threadIdx.x;
    const int lane = tid & 31;
    const int wid  = tid >> 5;
    const int wm   = wid & 1;        // co half (64)
    const int wn   = wid >> 1;       // 0..3 : output row within tile (n quarter of 64)
    const int lr   = lane >> 2;      // 0..7
    const int lc   = lane & 3;       // 0..3
    const int trot = wid;            // per-warp tap rotation (0..7)

    const int h0 = blockIdx.x * 4;
    const int b  = blockIdx.y;

    const uint32_t sbase = s2u(smf);
    const uint4* wsrc = g_wt4 + (size_t)b * 16 * WBUF_U4;

    // zero X buffers once (halo zeros are loop-invariant)
    for (int i = tid; i < 2 * XBUF_F; i += 256) smf[i] = 0.f;
    __syncthreads();

    float acc[4][8][4];
#pragma unroll
    for (int i = 0; i < 4; i++)
#pragma unroll
        for (int j = 0; j < 8; j++)
#pragma unroll
            for (int k = 0; k < 4; k++) acc[i][j][k] = 0.f;

    auto stageX = [&](int chunk, int xoff) {
#pragma unroll
        for (int it = 0; it < 3; it++) {
            int idx = tid + it * 256;            // [pair 4][row 6][seg 32]
            int pr  = idx / 192;
            int rem = idx - pr * 192;
            int row = rem >> 5;
            int seg = rem & 31;
            int gh  = h0 + row - 1;
            if ((unsigned)gh < (unsigned)Hh) {
                const uint4* src = (const uint4*)g_xt +
                    ((((size_t)b * 16 + chunk) * 4 + pr) * 64 + gh) * 32 + seg;
                uint32_t dst = sbase + 4u * (uint32_t)(xoff + pr * XP + row * XR + 8 + seg * 4);
                CP16(dst, src);
            }
        }
    };
    auto stageW = [&](int chunk, uint32_t woff_b) {
        const uint4* src = wsrc + (size_t)chunk * WBUF_U4;
#pragma unroll
        for (int it = 0; it < 9; it++) {
            int idx = tid + it * 256;            // 2304 uint4, contiguous copy
            CP16(sbase + woff_b + idx * 16u, src + idx);
        }
        asm volatile("cp.async.commit_group;" ::: "memory");
    };

    const uint32_t WBASE = 2 * XBUF_F * 4;       // byte offset of W buffers

    stageX(0, 0);
    stageW(0, WBASE);
    asm volatile("cp.async.wait_group 0;" ::: "memory");
    __syncthreads();

    for (int kc = 0; kc < 16; kc++) {
        const int cur = kc & 1;
        const int xoff = cur * XBUF_F;
        const uint4* wbuf = (const uint4*)((const char*)smf + WBASE + cur * (WBUF_U4 * 16));

        if (kc < 15) {
            stageX(kc + 1, (cur ^ 1) * XBUF_F);
            stageW(kc + 1, WBASE + (cur ^ 1) * (WBUF_U4 * 16));
        }

        const uint32_t* xwarp = smu + xoff + lc * XP + wn * XR + (lr + 3) * 2;

#pragma unroll
        for (int tp = 0; tp < 9; tp++) {
            int t = tp + trot;
            if (t >= 9) t -= 9;
            int kh = t / 3;
            int kw = t - kh * 3;

            uint4 a[4];
#pragma unroll
            for (int tm = 0; tm < 4; tm++) {
                const int cb = wm * 4 + tm;
                a[tm] = wbuf[(t * 8 + cb) * 32 + lr * 4 + lc];
            }
            const uint32_t* xq = xwarp + kh * XR + kw * 2;
#pragma unroll
            for (int tn = 0; tn < 8; tn++) {
                uint2 bb = *(const uint2*)(xq + tn * 16);
#pragma unroll
                for (int tm = 0; tm < 4; tm++)
                    MMA_TF32(acc[tm][tn], a[tm].x, a[tm].y, a[tm].z, a[tm].w, bb.x, bb.y);
            }
        }

        asm volatile("cp.async.wait_group 0;" ::: "memory");
        __syncthreads();
    }

    // epilogue: out = inp + conv
    const int h = h0 + wn;
#pragma unroll
    for (int tm = 0; tm < 4; tm++) {
#pragma unroll
        for (int tn = 0; tn < 8; tn++) {
            const int w = tn * 8 + lc * 2;
            const int co0 = wm * 64 + tm * 16 + lr;
#pragma unroll
            for (int half = 0; half < 2; half++) {
                const int co = co0 + half * 8;
                const size_t off = ((size_t)(b * Cc + co) * Hh + h) * Ww + w;
                float2 rv = *(const float2*)(inp + off);
                float2 ov;
                ov.x = rv.x + acc[tm][tn][half * 2 + 0];
                ov.y = rv.y + acc[tm][tn][half * 2 + 1];
                *(float2*)(out + off) = ov;
            }
        }
    }
}

extern "C" void kernel_launch(void* const* d_in, const int* in_sizes, int n_in,
                              void* d_out, int out_size)
{
    const float* inp = (const float*)d_in[0];   // [16,128,64,64]
    const float* wgt = (const float*)d_in[1];   // [16,128,128,3,3]
    float* out = (float*)d_out;

    cudaFuncSetAttribute(prep_w_t, cudaFuncAttributeMaxDynamicSharedMemorySize, 73728);
    prep_w_t<<<Bn * 8, 512, 73728>>>(wgt);
    prep_x<<<4096, 512>>>(inp);

    const int smem_bytes = 2 * XBUF_F * 4 + 2 * WBUF_U4 * 16;   // 29184 + 73728 = 102912
    cudaFuncSetAttribute(resconv_mma, cudaFuncAttributeMaxDynamicSharedMemorySize, smem_bytes);
    dim3 grid(Hh / 4, Bn);   // (16, 16) = 256 CTAs
    resconv_mma<<<grid, 256, smem_bytes>>>(inp, out);
}

// round 8
// speedup vs baseline: 1.2833x; 1.0303x over previous
#include <cuda_runtime.h>
#include <cstdint>

#define Bn 16
#define Cc 128
#define Hh 64
#define Ww 64

// ---- scratch ----
// g_wt4: W frag-vector layout, uint4[b][chunk16][tap9][cb8][r8][c4]
//   uint4 = tf32 { W(co=cb*16+r, k=c), W(co+8, k=c), W(co, k=c+4), W(co+8, k=c+4) },
//   k = ci within chunk — one m16n8k8 A-fragment per lane via LDS.128.
// g_xt: X tf32, pair-interleaved [b][chunk16][pair4][h][w-pair32] uint4.
__device__ uint4 g_wt4[(size_t)Bn * 16 * 9 * 8 * 8 * 4];
__device__ uint32_t g_xt[(size_t)Bn * Cc * Hh * Ww];

__device__ __forceinline__ uint32_t f2tf32(float x) {
    uint32_t r;
    asm("cvt.rna.tf32.f32 %0, %1;" : "=r"(r) : "f"(x));
    return r;
}

// ---- fused prep: blocks [0,128) = W smem-transpose; blocks [128, 4224) = X round ----
__global__ void prep_all(const float* __restrict__ w, const float* __restrict__ x) {
    extern __shared__ float s[];            // W blocks: [16 co][1152]
    if (blockIdx.x < 128) {
        const int b  = blockIdx.x >> 3;
        const int cb = blockIdx.x & 7;
        const float* src = w + ((size_t)b * Cc + cb * 16) * 1152;
#pragma unroll
        for (int it = 0; it < 9; it++) {
            int idx = threadIdx.x + it * 512;   // 4608 uint4
            ((uint4*)s)[idx] = ((const uint4*)src)[idx];
        }
        __syncthreads();
#pragma unroll
        for (int it = 0; it < 9; it++) {
            int idx  = threadIdx.x + it * 512;  // ((ch*9+t)*8+r)*4+c
            int c    = idx & 3;
            int r    = (idx >> 2) & 7;
            int rest = idx >> 5;
            int t    = rest % 9;
            int ch   = rest / 9;
            uint4 o;
            o.x = f2tf32(s[ r      * 1152 + (ch * 8 + c    ) * 9 + t]);
            o.y = f2tf32(s[(r + 8) * 1152 + (ch * 8 + c    ) * 9 + t]);
            o.z = f2tf32(s[ r      * 1152 + (ch * 8 + c + 4) * 9 + t]);
            o.w = f2tf32(s[(r + 8) * 1152 + (ch * 8 + c + 4) * 9 + t]);
            g_wt4[((((size_t)(b * 16 + ch) * 9 + t) * 8 + cb) * 8 + r) * 4 + c] = o;
        }
    } else {
        int u  = (blockIdx.x - 128) * 512 + threadIdx.x;   // 2097152 uint4s
        int w4 = u & 31;
        int h  = (u >> 5) & 63;
        int pr = (u >> 11) & 3;
        int ch = (u >> 13) & 15;
        int b  = u >> 17;
        int ci = ch * 8 + pr;
        const float* base = x + ((size_t)(b * Cc + ci) * Hh + h) * Ww + w4 * 2;
        float2 v0 = *(const float2*)base;
        float2 v1 = *(const float2*)(base + 4 * Hh * Ww);
        uint4 o;
        o.x = f2tf32(v0.x); o.y = f2tf32(v1.x);
        o.z = f2tf32(v0.y); o.w = f2tf32(v1.y);
        ((uint4*)g_xt)[u] = o;
    }
}

// ---- main kernel ----
// CTA: M=128 co x N=256 (4 rows x 64 w), 8 warps, warp tile 64x64. 16 K-chunks of 8 ci.
// X tile [4 pair][6 rows][76 slots][2]; pair stride XP=936 (==8 mod 32 -> conflict-free
// LDS.64 B-frags: banks 8*lc+2*lr distinct per 16-lane phase), row stride 152, w=0 at slot 4.
// W tile: 2304 uint4/buffer, contiguous copy of g_wt4 chunk; A-frag LDS.128 conflict-free.
#define XP 936
#define XR 152
#define XBUF_F (4 * XP)     // 3744
#define WBUF_U4 2304

__device__ __forceinline__ uint32_t s2u(const void* p) {
    uint32_t a;
    asm("{ .reg .u64 t; cvta.to.shared.u64 t, %1; cvt.u32.u64 %0, t; }" : "=r"(a) : "l"(p));
    return a;
}

#define CP16(dst_u32, src_ptr) \
    asm volatile("cp.async.cg.shared.global [%0], [%1], 16;" :: "r"(dst_u32), "l"(src_ptr))

#define MMA_TF32(c, a0, a1, a2, a3, b0v, b1v)                                     \
    asm volatile("mma.sync.aligned.m16n8k8.row.col.f32.tf32.tf32.f32 "            \
                 "{%0,%1,%2,%3}, {%4,%5,%6,%7}, {%8,%9}, {%0,%1,%2,%3};"          \
                 : "+f"((c)[0]), "+f"((c)[1]), "+f"((c)[2]), "+f"((c)[3])         \
                 : "r"(a0), "r"(a1), "r"(a2), "r"(a3), "r"(b0v), "r"(b1v))

__global__ __launch_bounds__(256, 1)
void resconv_mma(const float* __restrict__ inp, float* __restrict__ out)
{
    extern __shared__ float smf[];
    uint32_t* smu = (uint32_t*)smf;

    const int tid  = threadIdx.x;
    const int lane = tid & 31;
    const int wid  = tid >> 5;
    const int wm   = wid & 1;        // co half (64)
    const int wn   = wid >> 1;       // 0..3 : output row within tile
    const int lr   = lane >> 2;      // 0..7
    const int lc   = lane & 3;       // 0..3
    const int trot = wid;            // per-warp tap rotation

    const int h0 = blockIdx.x * 4;
    const int b  = blockIdx.y;

    const uint32_t sbase = s2u(smf);
    const uint4* wsrc = g_wt4 + (size_t)b * 16 * WBUF_U4;

    // zero X buffers once (halo zeros are loop-invariant)
    for (int i = tid; i < 2 * XBUF_F; i += 256) smf[i] = 0.f;
    __syncthreads();

    float acc[4][8][4];
#pragma unroll
    for (int i = 0; i < 4; i++)
#pragma unroll
        for (int j = 0; j < 8; j++)
#pragma unroll
            for (int k = 0; k < 4; k++) acc[i][j][k] = 0.f;

    auto stageX = [&](int chunk, int xoff) {
#pragma unroll
        for (int it = 0; it < 3; it++) {
            int idx = tid + it * 256;            // [pair 4][row 6][seg 32]
            int pr  = idx / 192;
            int rem = idx - pr * 192;
            int row = rem >> 5;
            int seg = rem & 31;
            int gh  = h0 + row - 1;
            if ((unsigned)gh < (unsigned)Hh) {
                const uint4* src = (const uint4*)g_xt +
                    ((((size_t)b * 16 + chunk) * 4 + pr) * 64 + gh) * 32 + seg;
                uint32_t dst = sbase + 4u * (uint32_t)(xoff + pr * XP + row * XR + 8 + seg * 4);
                CP16(dst, src);
            }
        }
    };
    auto stageW = [&](int chunk, uint32_t woff_b) {
        const uint4* src = wsrc + (size_t)chunk * WBUF_U4;
#pragma unroll
        for (int it = 0; it < 9; it++) {
            int idx = tid + it * 256;            // contiguous copy
            CP16(sbase + woff_b + idx * 16u, src + idx);
        }
        asm volatile("cp.async.commit_group;" ::: "memory");
    };

    const uint32_t WBASE = 2 * XBUF_F * 4;       // byte offset of W buffers

    stageX(0, 0);
    stageW(0, WBASE);
    asm volatile("cp.async.wait_group 0;" ::: "memory");
    __syncthreads();

    for (int kc = 0; kc < 16; kc++) {
        const int cur = kc & 1;
        const int xoff = cur * XBUF_F;
        const uint4* wbuf = (const uint4*)((const char*)smf + WBASE + cur * (WBUF_U4 * 16));

        if (kc < 15) {
            stageX(kc + 1, (cur ^ 1) * XBUF_F);
            stageW(kc + 1, WBASE + (cur ^ 1) * (WBUF_U4 * 16));
        }

        const uint32_t* xwarp = smu + xoff + lc * XP + wn * XR + (lr + 3) * 2;

#pragma unroll
        for (int tp = 0; tp < 9; tp++) {
            int t = tp + trot;
            if (t >= 9) t -= 9;
            int kh = t / 3;
            int kw = t - kh * 3;

            uint4 a[4];
#pragma unroll
            for (int tm = 0; tm < 4; tm++) {
                const int cb = wm * 4 + tm;
                a[tm] = wbuf[(t * 8 + cb) * 32 + lr * 4 + lc];
            }
            const uint32_t* xq = xwarp + kh * XR + kw * 2;
#pragma unroll
            for (int tn = 0; tn < 8; tn++) {
                uint2 bb = *(const uint2*)(xq + tn * 16);
#pragma unroll
                for (int tm = 0; tm < 4; tm++)
                    MMA_TF32(acc[tm][tn], a[tm].x, a[tm].y, a[tm].z, a[tm].w, bb.x, bb.y);
            }
        }

        asm volatile("cp.async.wait_group 0;" ::: "memory");
        __syncthreads();
    }

    // epilogue: out = inp + conv
    const int h = h0 + wn;
#pragma unroll
    for (int tm = 0; tm < 4; tm++) {
#pragma unroll
        for (int tn = 0; tn < 8; tn++) {
            const int w = tn * 8 + lc * 2;
            const int co0 = wm * 64 + tm * 16 + lr;
#pragma unroll
            for (int half = 0; half < 2; half++) {
                const int co = co0 + half * 8;
                const size_t off = ((size_t)(b * Cc + co) * Hh + h) * Ww + w;
                float2 rv = *(const float2*)(inp + off);
                float2 ov;
                ov.x = rv.x + acc[tm][tn][half * 2 + 0];
                ov.y = rv.y + acc[tm][tn][half * 2 + 1];
                *(float2*)(out + off) = ov;
            }
        }
    }
}

extern "C" void kernel_launch(void* const* d_in, const int* in_sizes, int n_in,
                              void* d_out, int out_size)
{
    const float* inp = (const float*)d_in[0];   // [16,128,64,64]
    const float* wgt = (const float*)d_in[1];   // [16,128,128,3,3]
    float* out = (float*)d_out;

    cudaFuncSetAttribute(prep_all, cudaFuncAttributeMaxDynamicSharedMemorySize, 73728);
    prep_all<<<128 + 4096, 512, 73728>>>(wgt, inp);

    const int smem_bytes = 2 * XBUF_F * 4 + 2 * WBUF_U4 * 16;   // 29952 + 73728 = 103680
    cudaFuncSetAttribute(resconv_mma, cudaFuncAttributeMaxDynamicSharedMemorySize, smem_bytes);
    dim3 grid(Hh / 4, Bn);   // (16, 16) = 256 CTAs
    resconv_mma<<<grid, 256, smem_bytes>>>(inp, out);
}

// round 9
// speedup vs baseline: 1.3289x; 1.0355x over previous
#include <cuda_runtime.h>
#include <cstdint>

#define Bn 16
#define Cc 128
#define Hh 64
#define Ww 64

// ---- scratch ----
// g_wt4: W frag-vector layout, uint4[b][chunk16][tap9][cb8][r8][c4]
//   uint4 = tf32 { W(co=cb*16+r, k=c), W(co+8, k=c), W(co, k=c+4), W(co+8, k=c+4) },
//   k = ci within chunk — one m16n8k8 A-fragment per lane via LDS.128.
// g_xt: X tf32, pair-interleaved [b][chunk16][pair4][h][w-pair32] uint4.
__device__ uint4 g_wt4[(size_t)Bn * 16 * 9 * 8 * 8 * 4];
__device__ uint32_t g_xt[(size_t)Bn * Cc * Hh * Ww];

__device__ __forceinline__ uint32_t f2tf32(float x) {
    uint32_t r;
    asm("cvt.rna.tf32.f32 %0, %1;" : "=r"(r) : "f"(x));
    return r;
}

// ---- fused prep: blocks [0,128) = W smem-transpose; blocks [128, 4224) = X round ----
__global__ void prep_all(const float* __restrict__ w, const float* __restrict__ x) {
    extern __shared__ float s[];            // W blocks: [16 co][1152]
    if (blockIdx.x < 128) {
        const int b  = blockIdx.x >> 3;
        const int cb = blockIdx.x & 7;
        const float* src = w + ((size_t)b * Cc + cb * 16) * 1152;
#pragma unroll
        for (int it = 0; it < 9; it++) {
            int idx = threadIdx.x + it * 512;   // 4608 uint4
            ((uint4*)s)[idx] = ((const uint4*)src)[idx];
        }
        __syncthreads();
#pragma unroll
        for (int it = 0; it < 9; it++) {
            int idx  = threadIdx.x + it * 512;  // ((ch*9+t)*8+r)*4+c
            int c    = idx & 3;
            int r    = (idx >> 2) & 7;
            int rest = idx >> 5;
            int t    = rest % 9;
            int ch   = rest / 9;
            uint4 o;
            o.x = f2tf32(s[ r      * 1152 + (ch * 8 + c    ) * 9 + t]);
            o.y = f2tf32(s[(r + 8) * 1152 + (ch * 8 + c    ) * 9 + t]);
            o.z = f2tf32(s[ r      * 1152 + (ch * 8 + c + 4) * 9 + t]);
            o.w = f2tf32(s[(r + 8) * 1152 + (ch * 8 + c + 4) * 9 + t]);
            g_wt4[((((size_t)(b * 16 + ch) * 9 + t) * 8 + cb) * 8 + r) * 4 + c] = o;
        }
    } else {
        int u  = (blockIdx.x - 128) * 512 + threadIdx.x;   // 2097152 uint4s
        int w4 = u & 31;
        int h  = (u >> 5) & 63;
        int pr = (u >> 11) & 3;
        int ch = (u >> 13) & 15;
        int b  = u >> 17;
        int ci = ch * 8 + pr;
        const float* base = x + ((size_t)(b * Cc + ci) * Hh + h) * Ww + w4 * 2;
        float2 v0 = *(const float2*)base;
        float2 v1 = *(const float2*)(base + 4 * Hh * Ww);
        uint4 o;
        o.x = f2tf32(v0.x); o.y = f2tf32(v1.x);
        o.z = f2tf32(v0.y); o.w = f2tf32(v1.y);
        ((uint4*)g_xt)[u] = o;
    }
}

// ---- main kernel ----
// M-split: CTA = M=64 (one co half) x N=256 (4 rows x 64 w), 4 warps, warp tile 64x64,
// 128 threads, 2 CTAs/SM. 16 K-chunks of 8 ci.
// X tile [4 pair][6 rows][76 slots][2]; pair stride XP=936 (==8 mod 32, conflict-free
// LDS.64 B-frags), row stride 152, w=0 at slot 4.
// W tile: 1152 uint4/buffer = this CTA's co-half of the g_wt4 chunk ([tap9][cb4][r8][c4]).
#define XP 936
#define XR 152
#define XBUF_F (4 * XP)     // 3744
#define WBUF_U4 1152

__device__ __forceinline__ uint32_t s2u(const void* p) {
    uint32_t a;
    asm("{ .reg .u64 t; cvta.to.shared.u64 t, %1; cvt.u32.u64 %0, t; }" : "=r"(a) : "l"(p));
    return a;
}

#define CP16(dst_u32, src_ptr) \
    asm volatile("cp.async.cg.shared.global [%0], [%1], 16;" :: "r"(dst_u32), "l"(src_ptr))

#define MMA_TF32(c, a0, a1, a2, a3, b0v, b1v)                                     \
    asm volatile("mma.sync.aligned.m16n8k8.row.col.f32.tf32.tf32.f32 "            \
                 "{%0,%1,%2,%3}, {%4,%5,%6,%7}, {%8,%9}, {%0,%1,%2,%3};"          \
                 : "+f"((c)[0]), "+f"((c)[1]), "+f"((c)[2]), "+f"((c)[3])         \
                 : "r"(a0), "r"(a1), "r"(a2), "r"(a3), "r"(b0v), "r"(b1v))

__global__ __launch_bounds__(128, 2)
void resconv_mma(const float* __restrict__ inp, float* __restrict__ out)
{
    extern __shared__ float smf[];
    uint32_t* smu = (uint32_t*)smf;

    const int tid  = threadIdx.x;
    const int lane = tid & 31;
    const int wid  = tid >> 5;       // 0..3 : output row within tile (n quarter)
    const int lr   = lane >> 2;      // 0..7
    const int lc   = lane & 3;       // 0..3
    const int trot = wid * 2;        // per-warp tap rotation (0,2,4,6)

    const int h0  = blockIdx.x * 4;
    const int b   = blockIdx.y;
    const int wmH = blockIdx.z;      // co half of this CTA

    const uint32_t sbase = s2u(smf);
    const uint4* wsrc = g_wt4 + (size_t)b * 16 * 2304;   // full-chunk stride = 2304 uint4

    // zero X buffers once (halo zeros are loop-invariant)
    for (int i = tid; i < 2 * XBUF_F; i += 128) smf[i] = 0.f;
    __syncthreads();

    float acc[4][8][4];
#pragma unroll
    for (int i = 0; i < 4; i++)
#pragma unroll
        for (int j = 0; j < 8; j++)
#pragma unroll
            for (int k = 0; k < 4; k++) acc[i][j][k] = 0.f;

    auto stageX = [&](int chunk, int xoff) {
#pragma unroll
        for (int it = 0; it < 6; it++) {
            int idx = tid + it * 128;            // [pair 4][row 6][seg 32] = 768
            int pr  = idx / 192;
            int rem = idx - pr * 192;
            int row = rem >> 5;
            int seg = rem & 31;
            int gh  = h0 + row - 1;
            if ((unsigned)gh < (unsigned)Hh) {
                const uint4* src = (const uint4*)g_xt +
                    ((((size_t)b * 16 + chunk) * 4 + pr) * 64 + gh) * 32 + seg;
                uint32_t dst = sbase + 4u * (uint32_t)(xoff + pr * XP + row * XR + 8 + seg * 4);
                CP16(dst, src);
            }
        }
    };
    auto stageW = [&](int chunk, uint32_t woff_b) {
        const uint4* src = wsrc + (size_t)chunk * 2304;
#pragma unroll
        for (int it = 0; it < 9; it++) {
            int idx  = tid + it * 128;           // 0..1151
            int tap  = idx >> 7;
            int rest = idx & 127;                // cb4 x r8 x c4 within this co-half
            CP16(sbase + woff_b + idx * 16u, src + tap * 256 + wmH * 128 + rest);
        }
        asm volatile("cp.async.commit_group;" ::: "memory");
    };

    const uint32_t WBASE = 2 * XBUF_F * 4;       // byte offset of W buffers

    stageX(0, 0);
    stageW(0, WBASE);
    asm volatile("cp.async.wait_group 0;" ::: "memory");
    __syncthreads();

    for (int kc = 0; kc < 16; kc++) {
        const int cur = kc & 1;
        const int xoff = cur * XBUF_F;
        const uint4* wbuf = (const uint4*)((const char*)smf + WBASE + cur * (WBUF_U4 * 16));

        if (kc < 15) {
            stageX(kc + 1, (cur ^ 1) * XBUF_F);
            stageW(kc + 1, WBASE + (cur ^ 1) * (WBUF_U4 * 16));
        }

        const uint32_t* xwarp = smu + xoff + lc * XP + wid * XR + (lr + 3) * 2;

#pragma unroll
        for (int tp = 0; tp < 9; tp++) {
            int t = tp + trot;
            if (t >= 9) t -= 9;
            int kh = t / 3;
            int kw = t - kh * 3;

            uint4 a[4];
#pragma unroll
            for (int tm = 0; tm < 4; tm++)
                a[tm] = wbuf[t * 128 + tm * 32 + lr * 4 + lc];

            const uint32_t* xq = xwarp + kh * XR + kw * 2;
#pragma unroll
            for (int tn = 0; tn < 8; tn++) {
                uint2 bb = *(const uint2*)(xq + tn * 16);
#pragma unroll
                for (int tm = 0; tm < 4; tm++)
                    MMA_TF32(acc[tm][tn], a[tm].x, a[tm].y, a[tm].z, a[tm].w, bb.x, bb.y);
            }
        }

        asm volatile("cp.async.wait_group 0;" ::: "memory");
        __syncthreads();
    }

    // epilogue: out = inp + conv  (this warp: row h0+wid, all 64 w, this co-half)
    const int h = h0 + wid;
#pragma unroll
    for (int tm = 0; tm < 4; tm++) {
#pragma unroll
        for (int tn = 0; tn < 8; tn++) {
            const int w = tn * 8 + lc * 2;
            const int co0 = wmH * 64 + tm * 16 + lr;
#pragma unroll
            for (int half = 0; half < 2; half++) {
                const int co = co0 + half * 8;
                const size_t off = ((size_t)(b * Cc + co) * Hh + h) * Ww + w;
                float2 rv = *(const float2*)(inp + off);
                float2 ov;
                ov.x = rv.x + acc[tm][tn][half * 2 + 0];
                ov.y = rv.y + acc[tm][tn][half * 2 + 1];
                *(float2*)(out + off) = ov;
            }
        }
    }
}

extern "C" void kernel_launch(void* const* d_in, const int* in_sizes, int n_in,
                              void* d_out, int out_size)
{
    const float* inp = (const float*)d_in[0];   // [16,128,64,64]
    const float* wgt = (const float*)d_in[1];   // [16,128,128,3,3]
    float* out = (float*)d_out;

    cudaFuncSetAttribute(prep_all, cudaFuncAttributeMaxDynamicSharedMemorySize, 73728);
    prep_all<<<128 + 4096, 512, 73728>>>(wgt, inp);

    const int smem_bytes = 2 * XBUF_F * 4 + 2 * WBUF_U4 * 16;   // 29952 + 36864 = 66816
    cudaFuncSetAttribute(resconv_mma, cudaFuncAttributeMaxDynamicSharedMemorySize, smem_bytes);
    dim3 grid(Hh / 4, Bn, 2);   // (16, 16, 2) = 512 CTAs, 2/SM
    resconv_mma<<<grid, 128, smem_bytes>>>(inp, out);
}

// round 10
// speedup vs baseline: 2.2204x; 1.6709x over previous
#include <cuda_runtime.h>
#include <cuda_fp16.h>
#include <cstdint>

#define Bn 16
#define Cc 128
#define Hh 64
#define Ww 64

// ---- scratch ----
// g_wh: W fp16 A-fragment-vector layout, uint4[b][chunk8][tap9][cb8][r8][c4]
//   uint4 = fp16x2 regs {a0,a1,a2,a3} of m16n8k16: co = cb*16+r (+8 for a1/a3),
//   k = 2c,2c+1 (a0/a1) and 2c+8,2c+9 (a2/a3), k = ci within 16-ci chunk.
// g_xh: X fp16 pair-interleaved uint4[b][chunk8][pp4][h64][seg32]:
//   uint4 = { (w0: k=2pp,2pp+1), (w0: k=2pp+8,2pp+9), (w0+1: ...), (w0+1: ...) }, w0 = seg*2.
__device__ uint4 g_wh[(size_t)Bn * 8 * 9 * 8 * 8 * 4];
__device__ uint4 g_xh[(size_t)Bn * 8 * 4 * 64 * 32];

__device__ __forceinline__ uint32_t h2(float a, float b) {
    __half2 h = __floats2half2_rn(a, b);
    return *(uint32_t*)&h;
}

// ---- fused prep: blocks [0,128) = W smem-transpose; [128, 2176) = X pack ----
__global__ void prep_all(const float* __restrict__ w, const float* __restrict__ x) {
    extern __shared__ float s[];            // W blocks: [16 co][1152]
    if (blockIdx.x < 128) {
        const int b  = blockIdx.x >> 3;
        const int cb = blockIdx.x & 7;
        const float* src = w + ((size_t)b * Cc + cb * 16) * 1152;
#pragma unroll
        for (int it = 0; it < 9; it++) {
            int idx = threadIdx.x + it * 512;   // 4608 uint4
            ((uint4*)s)[idx] = ((const uint4*)src)[idx];
        }
        __syncthreads();
#pragma unroll
        for (int it = 0; it < 5; it++) {
            int idx = threadIdx.x + it * 512;   // 2304 outputs
            if (idx < 2304) {
                int c    = idx & 3;
                int r    = (idx >> 2) & 7;
                int rest = idx >> 5;
                int t    = rest % 9;
                int ch   = rest / 9;            // 0..7
                int k0   = ch * 16 + 2 * c;
                uint4 o;
                o.x = h2(s[ r      * 1152 + (k0    ) * 9 + t], s[ r      * 1152 + (k0 + 1) * 9 + t]);
                o.y = h2(s[(r + 8) * 1152 + (k0    ) * 9 + t], s[(r + 8) * 1152 + (k0 + 1) * 9 + t]);
                o.z = h2(s[ r      * 1152 + (k0 + 8) * 9 + t], s[ r      * 1152 + (k0 + 9) * 9 + t]);
                o.w = h2(s[(r + 8) * 1152 + (k0 + 8) * 9 + t], s[(r + 8) * 1152 + (k0 + 9) * 9 + t]);
                g_wh[((((size_t)(b * 8 + ch) * 9 + t) * 8 + cb) * 8 + r) * 4 + c] = o;
            }
        }
    } else {
        int u   = (blockIdx.x - 128) * 512 + threadIdx.x;  // 1048576 uint4s
        int seg = u & 31;
        int h   = (u >> 5) & 63;
        int pp  = (u >> 11) & 3;
        int ch  = (u >> 13) & 7;
        int b   = u >> 16;
        int ci0 = ch * 16 + 2 * pp;
        int w0  = seg * 2;
        const float* base = x + ((size_t)(b * Cc + ci0) * Hh + h) * Ww + w0;
        float2 e0 = *(const float2*)(base);                     // ci0
        float2 e1 = *(const float2*)(base +     Hh * Ww);       // ci0+1
        float2 e8 = *(const float2*)(base + 8 * Hh * Ww);       // ci0+8
        float2 e9 = *(const float2*)(base + 9 * Hh * Ww);       // ci0+9
        uint4 o;
        o.x = h2(e0.x, e1.x);   // w0,   b0-pair
        o.y = h2(e8.x, e9.x);   // w0,   b1-pair
        o.z = h2(e0.y, e1.y);   // w0+1, b0-pair
        o.w = h2(e8.y, e9.y);   // w0+1, b1-pair
        g_xh[u] = o;
    }
}

// ---- main kernel ----
// M-split: CTA = M=64 (one co half) x N=256 (4 rows x 64 w), 4 warps, warp tile 64x64,
// 128 threads, 2 CTAs/SM. 8 K-chunks of 16 ci, m16n8k16 fp16 MMA.
// X tile [4 pp][6 rows][76 slots][2 u32]; pair stride XP=936 u32 (==8 mod 32 -> conflict-free
// LDS.64 B-frags), row stride 152, w=0 at slot 4; each u32 = fp16x2 ci-pair.
// W tile: 1152 uint4/buffer = this CTA's co-half of a g_wh chunk ([tap9][cb4][r8][c4]).
#define XP 936
#define XR 152
#define XBUF_F (4 * XP)     // 3744 u32
#define WBUF_U4 1152

__device__ __forceinline__ uint32_t s2u(const void* p) {
    uint32_t a;
    asm("{ .reg .u64 t; cvta.to.shared.u64 t, %1; cvt.u32.u64 %0, t; }" : "=r"(a) : "l"(p));
    return a;
}

#define CP16(dst_u32, src_ptr) \
    asm volatile("cp.async.cg.shared.global [%0], [%1], 16;" :: "r"(dst_u32), "l"(src_ptr))

#define MMA_F16(c, a0, a1, a2, a3, b0v, b1v)                                      \
    asm volatile("mma.sync.aligned.m16n8k16.row.col.f32.f16.f16.f32 "             \
                 "{%0,%1,%2,%3}, {%4,%5,%6,%7}, {%8,%9}, {%0,%1,%2,%3};"          \
                 : "+f"((c)[0]), "+f"((c)[1]), "+f"((c)[2]), "+f"((c)[3])         \
                 : "r"(a0), "r"(a1), "r"(a2), "r"(a3), "r"(b0v), "r"(b1v))

__global__ __launch_bounds__(128, 2)
void resconv_mma(const float* __restrict__ inp, float* __restrict__ out)
{
    extern __shared__ float smf[];
    uint32_t* smu = (uint32_t*)smf;

    const int tid  = threadIdx.x;
    const int lane = tid & 31;
    const int wid  = tid >> 5;       // 0..3 : output row within tile
    const int lr   = lane >> 2;      // 0..7
    const int lc   = lane & 3;       // 0..3
    const int trot = wid * 2;        // per-warp tap rotation (0,2,4,6)

    const int h0  = blockIdx.x * 4;
    const int b   = blockIdx.y;
    const int wmH = blockIdx.z;      // co half of this CTA

    const uint32_t sbase = s2u(smf);
    const uint4* wsrc = g_wh + (size_t)b * 8 * 2304;   // full-chunk stride = 2304 uint4

    // zero X buffers once (halo zeros are loop-invariant; fp16 zero == bits zero)
    for (int i = tid; i < 2 * XBUF_F; i += 128) smf[i] = 0.f;
    __syncthreads();

    float acc[4][8][4];
#pragma unroll
    for (int i = 0; i < 4; i++)
#pragma unroll
        for (int j = 0; j < 8; j++)
#pragma unroll
            for (int k = 0; k < 4; k++) acc[i][j][k] = 0.f;

    auto stageX = [&](int chunk, int xoff) {
#pragma unroll
        for (int it = 0; it < 6; it++) {
            int idx = tid + it * 128;            // [pp 4][row 6][seg 32] = 768
            int pr  = idx / 192;
            int rem = idx - pr * 192;
            int row = rem >> 5;
            int seg = rem & 31;
            int gh  = h0 + row - 1;
            if ((unsigned)gh < (unsigned)Hh) {
                const uint4* src = g_xh +
                    ((((size_t)b * 8 + chunk) * 4 + pr) * 64 + gh) * 32 + seg;
                uint32_t dst = sbase + 4u * (uint32_t)(xoff + pr * XP + row * XR + 8 + seg * 4);
                CP16(dst, src);
            }
        }
    };
    auto stageW = [&](int chunk, uint32_t woff_b) {
        const uint4* src = wsrc + (size_t)chunk * 2304;
#pragma unroll
        for (int it = 0; it < 9; it++) {
            int idx  = tid + it * 128;           // 0..1151
            int tap  = idx >> 7;
            int rest = idx & 127;                // cb4 x r8 x c4 within this co-half
            CP16(sbase + woff_b + idx * 16u, src + tap * 256 + wmH * 128 + rest);
        }
        asm volatile("cp.async.commit_group;" ::: "memory");
    };

    const uint32_t WBASE = 2 * XBUF_F * 4;       // byte offset of W buffers

    stageX(0, 0);
    stageW(0, WBASE);
    asm volatile("cp.async.wait_group 0;" ::: "memory");
    __syncthreads();

    for (int kc = 0; kc < 8; kc++) {
        const int cur = kc & 1;
        const int xoff = cur * XBUF_F;
        const uint4* wbuf = (const uint4*)((const char*)smf + WBASE + cur * (WBUF_U4 * 16));

        if (kc < 7) {
            stageX(kc + 1, (cur ^ 1) * XBUF_F);
            stageW(kc + 1, WBASE + (cur ^ 1) * (WBUF_U4 * 16));
        }

        const uint32_t* xwarp = smu + xoff + lc * XP + wid * XR + (lr + 3) * 2;

#pragma unroll
        for (int tp = 0; tp < 9; tp++) {
            int t = tp + trot;
            if (t >= 9) t -= 9;
            int kh = t / 3;
            int kw = t - kh * 3;

            uint4 a[4];
#pragma unroll
            for (int tm = 0; tm < 4; tm++)
                a[tm] = wbuf[t * 128 + tm * 32 + lr * 4 + lc];

            const uint32_t* xq = xwarp + kh * XR + kw * 2;
#pragma unroll
            for (int tn = 0; tn < 8; tn++) {
                uint2 bb = *(const uint2*)(xq + tn * 16);
#pragma unroll
                for (int tm = 0; tm < 4; tm++)
                    MMA_F16(acc[tm][tn], a[tm].x, a[tm].y, a[tm].z, a[tm].w, bb.x, bb.y);
            }
        }

        asm volatile("cp.async.wait_group 0;" ::: "memory");
        __syncthreads();
    }

    // epilogue: out = inp + conv  (this warp: row h0+wid, all 64 w, this co-half)
    const int h = h0 + wid;
#pragma unroll
    for (int tm = 0; tm < 4; tm++) {
#pragma unroll
        for (int tn = 0; tn < 8; tn++) {
            const int w = tn * 8 + lc * 2;
            const int co0 = wmH * 64 + tm * 16 + lr;
#pragma unroll
            for (int half = 0; half < 2; half++) {
                const int co = co0 + half * 8;
                const size_t off = ((size_t)(b * Cc + co) * Hh + h) * Ww + w;
                float2 rv = *(const float2*)(inp + off);
                float2 ov;
                ov.x = rv.x + acc[tm][tn][half * 2 + 0];
                ov.y = rv.y + acc[tm][tn][half * 2 + 1];
                *(float2*)(out + off) = ov;
            }
        }
    }
}

extern "C" void kernel_launch(void* const* d_in, const int* in_sizes, int n_in,
                              void* d_out, int out_size)
{
    const float* inp = (const float*)d_in[0];   // [16,128,64,64]
    const float* wgt = (const float*)d_in[1];   // [16,128,128,3,3]
    float* out = (float*)d_out;

    cudaFuncSetAttribute(prep_all, cudaFuncAttributeMaxDynamicSharedMemorySize, 73728);
    prep_all<<<128 + 2048, 512, 73728>>>(wgt, inp);

    const int smem_bytes = 2 * XBUF_F * 4 + 2 * WBUF_U4 * 16;   // 29952 + 36864 = 66816
    cudaFuncSetAttribute(resconv_mma, cudaFuncAttributeMaxDynamicSharedMemorySize, smem_bytes);
    dim3 grid(Hh / 4, Bn, 2);   // (16, 16, 2) = 512 CTAs, 2/SM
    resconv_mma<<<grid, 128, smem_bytes>>>(inp, out);
}